// round 13
// baseline (speedup 1.0000x reference)
#include <cuda_runtime.h>
#include <cuda_fp16.h>
#include <cstdint>
#include <math.h>

constexpr int Tt = 512, NHc = 64, Dd = 512, Bb = 4;
constexpr int NHEADS = Bb * NHc;        // 256
constexpr int MPROJ  = Bb * Tt * NHc;   // 131072

// Scratch (device globals; no cudaMalloc allowed)
__device__ __half g_Wq[(size_t)Dd * Dd];
__device__ __half g_Wk[(size_t)Dd * Dd];
__device__ __half g_Wv[(size_t)Dd * Dd];
__device__ __half g_Q [(size_t)MPROJ * Dd];        // [B,N,T,D] head-major
__device__ __half g_K [(size_t)MPROJ * Dd];        // [B,N,S,D] head-major
__device__ __half g_V [(size_t)MPROJ * Dd];        // [B,N,S,D] head-major

__device__ __forceinline__ uint32_t smem_u32(const void* p) {
    uint32_t a;
    asm("{ .reg .u64 t; cvta.to.shared.u64 t, %1; cvt.u32.u64 %0, t; }" : "=r"(a) : "l"(p));
    return a;
}
__device__ __forceinline__ void cp_async16(uint32_t saddr, const void* gptr) {
    asm volatile("cp.async.cg.shared.global [%0], [%1], 16;" :: "r"(saddr), "l"(gptr));
}
__device__ __forceinline__ void cp_commit() {
    asm volatile("cp.async.commit_group;" ::: "memory");
}
template<int N> __device__ __forceinline__ void cp_wait() {
    asm volatile("cp.async.wait_group %0;" :: "n"(N) : "memory");
}
__device__ __forceinline__ void ldsm_x4(uint32_t& r0, uint32_t& r1, uint32_t& r2, uint32_t& r3,
                                        uint32_t a) {
    asm volatile("ldmatrix.sync.aligned.m8n8.x4.shared.b16 {%0,%1,%2,%3}, [%4];"
                 : "=r"(r0), "=r"(r1), "=r"(r2), "=r"(r3) : "r"(a));
}
__device__ __forceinline__ void ldsm_x4_t(uint32_t& r0, uint32_t& r1, uint32_t& r2, uint32_t& r3,
                                          uint32_t a) {
    asm volatile("ldmatrix.sync.aligned.m8n8.x4.trans.shared.b16 {%0,%1,%2,%3}, [%4];"
                 : "=r"(r0), "=r"(r1), "=r"(r2), "=r"(r3) : "r"(a));
}
__device__ __forceinline__ void mma_f16(float& d0, float& d1, float& d2, float& d3,
                                        uint32_t a0, uint32_t a1, uint32_t a2, uint32_t a3,
                                        uint32_t b0, uint32_t b1) {
    asm volatile(
        "mma.sync.aligned.m16n8k16.row.col.f32.f16.f16.f32 "
        "{%0,%1,%2,%3}, {%4,%5,%6,%7}, {%8,%9}, {%0,%1,%2,%3};"
        : "+f"(d0), "+f"(d1), "+f"(d2), "+f"(d3)
        : "r"(a0), "r"(a1), "r"(a2), "r"(a3), "r"(b0), "r"(b1));
}
__device__ __forceinline__ float decay_log(float gamma, int dt) {
    float gd = gamma * fabsf((float)dt) * (1.0f / 511.0f);
    return (gd < 11.0f) ? -gd : logf(expf(-gd) + 1e-8f);
}

// ---------------- W f32 -> f16 (one launch for Wq/Wk/Wv) ----------------
__global__ __launch_bounds__(256)
void w_to_half(const float* __restrict__ wq, const float* __restrict__ wk,
               const float* __restrict__ wv)
{
    const float* src = (blockIdx.y == 0) ? wq : (blockIdx.y == 1) ? wk : wv;
    __half* dst = (blockIdx.y == 0) ? g_Wq : (blockIdx.y == 1) ? g_Wk : g_Wv;
    size_t i = (size_t)blockIdx.x * blockDim.x + threadIdx.x;   // float4 index
    float4 v = ((const float4*)src)[i];
    __half2 h0 = __floats2half2_rn(v.x, v.y);
    __half2 h1 = __floats2half2_rn(v.z, v.w);
    uint2 u = { *(uint32_t*)&h0, *(uint32_t*)&h1 };
    ((uint2*)dst)[i] = u;
}

// ---------------- Projection GEMM (A read directly from f32 H) ----------------
// ONE launch covers Q/K/V via blockIdx.z; grid (4 n-tiles, 1024 m-tiles, 3).
// A path: LDG f32 -> cvt f16 -> STS (register-staged, overlapped with MMA).
// B path: cp.async from pre-converted f16 W.
__global__ __launch_bounds__(256, 2)
void proj_gemm(const float* __restrict__ Hi, const float* __restrict__ Hj,
               const float* __restrict__ bq, const float* __restrict__ bk,
               const float* __restrict__ bv)
{
    extern __shared__ __half sm[];   // 3 bufs x (A 16KB | B 16KB) = 96KB
    const uint32_t smbase = smem_u32(sm);

    const int tid = threadIdx.x;
    const int wid = tid >> 5, lane = tid & 31;
    const int wm = wid >> 2, wn = wid & 3;
    const int m0 = blockIdx.y * 128;
    const int n0 = blockIdx.x * 128;
    const int which = blockIdx.z;

    const float* Ag = (which == 0) ? Hi : Hj;
    const __half* Bg = ((which == 0) ? g_Wq : (which == 1) ? g_Wk : g_Wv) + (size_t)n0 * 512;
    const float* bias = (which == 0) ? bq : (which == 1) ? bk : bv;

    // staging split: thread -> row tid>>1, f16-chunks (tid&1)*4 .. +3 of 128B rows
    const int srow = tid >> 1;
    const int cb0  = (tid & 1) * 4;
    const float*  agp = Ag + (size_t)(m0 + srow) * 512 + cb0 * 8;
    const __half* bgp = Bg + (size_t)srow * 512 + cb0 * 8;
    uint32_t swoff[4];
#pragma unroll
    for (int i = 0; i < 4; i++)
        swoff[i] = (uint32_t)srow * 128 + (uint32_t)(((cb0 + i) ^ (srow & 7)) << 4);

    uint32_t hA[16];   // staged A for next stage (4 chunks x 16B f16)
    auto ldA = [&](int s) {
#pragma unroll
        for (int i = 0; i < 4; i++) {
            float4 u = *(const float4*)(agp + s * 64 + i * 8);
            float4 v = *(const float4*)(agp + s * 64 + i * 8 + 4);
            __half2 h0 = __floats2half2_rn(u.x, u.y);
            __half2 h1 = __floats2half2_rn(u.z, u.w);
            __half2 h2 = __floats2half2_rn(v.x, v.y);
            __half2 h3 = __floats2half2_rn(v.z, v.w);
            hA[i * 4 + 0] = *(uint32_t*)&h0;
            hA[i * 4 + 1] = *(uint32_t*)&h1;
            hA[i * 4 + 2] = *(uint32_t*)&h2;
            hA[i * 4 + 3] = *(uint32_t*)&h3;
        }
    };
    auto stsA = [&](int s) {
        char* ab = (char*)sm + (s % 3) * 32768;
#pragma unroll
        for (int i = 0; i < 4; i++) {
            uint4 v = { hA[i * 4 + 0], hA[i * 4 + 1], hA[i * 4 + 2], hA[i * 4 + 3] };
            *(uint4*)(ab + swoff[i]) = v;
        }
    };
    auto issueB = [&](int s) {
        uint32_t bb = smbase + (uint32_t)(s % 3) * 32768 + 16384;
        const __half* bg = bgp + s * 64;
#pragma unroll
        for (int i = 0; i < 4; i++)
            cp_async16(bb + swoff[i], bg + i * 8);
        cp_commit();
    };

    const int mfrag = wm * 64, nfrag = wn * 32;
    const int aChunkLo = lane >> 4;
    const int bChunkLo = (lane >> 3) & 1;
    uint32_t aRowOff[4]; int aSw[4];
#pragma unroll
    for (int mt = 0; mt < 4; mt++) {
        int row = mfrag + mt * 16 + (lane & 15);
        aRowOff[mt] = (uint32_t)row * 128; aSw[mt] = row & 7;
    }
    uint32_t bRowOff[2]; int bSw[2];
#pragma unroll
    for (int ntp = 0; ntp < 2; ntp++) {
        int row = nfrag + ntp * 16 + (lane & 7) + ((lane >> 4) << 3);
        bRowOff[ntp] = (uint32_t)row * 128; bSw[ntp] = row & 7;
    }

    float acc[4][4][4];
#pragma unroll
    for (int mt = 0; mt < 4; mt++)
#pragma unroll
        for (int nt = 0; nt < 4; nt++)
#pragma unroll
            for (int e = 0; e < 4; e++) acc[mt][nt][e] = 0.f;

    ldA(0);
    issueB(0); issueB(1);
#pragma unroll 1
    for (int s = 0; s < 8; s++) {
        stsA(s);
        if (s < 7) cp_wait<1>(); else cp_wait<0>();
        __syncthreads();
        if (s + 1 < 8) ldA(s + 1);   // LDG for next stage overlaps this stage's MMAs
        uint32_t ab = smbase + (uint32_t)(s % 3) * 32768;
        uint32_t bb = ab + 16384;
#pragma unroll
        for (int ks = 0; ks < 4; ks++) {
            uint32_t afr[4][4], bfr[4][2];
#pragma unroll
            for (int mt = 0; mt < 4; mt++)
                ldsm_x4(afr[mt][0], afr[mt][1], afr[mt][2], afr[mt][3],
                        ab + aRowOff[mt] + (uint32_t)(((ks * 2 + aChunkLo) ^ aSw[mt]) << 4));
#pragma unroll
            for (int ntp = 0; ntp < 2; ntp++) {
                uint32_t r0, r1, r2, r3;
                ldsm_x4(r0, r1, r2, r3,
                        bb + bRowOff[ntp] + (uint32_t)(((ks * 2 + bChunkLo) ^ bSw[ntp]) << 4));
                bfr[2 * ntp][0] = r0; bfr[2 * ntp][1] = r1;
                bfr[2 * ntp + 1][0] = r2; bfr[2 * ntp + 1][1] = r3;
            }
#pragma unroll
            for (int mt = 0; mt < 4; mt++)
#pragma unroll
                for (int nt = 0; nt < 4; nt++)
                    mma_f16(acc[mt][nt][0], acc[mt][nt][1], acc[mt][nt][2], acc[mt][nt][3],
                            afr[mt][0], afr[mt][1], afr[mt][2], afr[mt][3],
                            bfr[nt][0], bfr[nt][1]);
        }
        if (s + 2 < 8) issueB(s + 2);
    }

    const int rq = lane >> 2, kq = lane & 3;
    __half* outp = (which == 0) ? g_Q : (which == 1) ? g_K : g_V;
#pragma unroll
    for (int mt = 0; mt < 4; mt++) {
        const int m = m0 + mfrag + mt * 16 + rq;
        const int b = m >> 15, t = (m >> 6) & 511, n = m & 63;
        __half* dst0 = outp + ((size_t)((b * NHc + n) * Tt + t)) * 512;
#pragma unroll
        for (int nt = 0; nt < 4; nt++) {
            const int c = n0 + nfrag + nt * 8 + kq * 2;
            float2 bv = *(const float2*)(bias + c);
            *(__half2*)(dst0 + c) =
                __floats2half2_rn(acc[mt][nt][0] + bv.x, acc[mt][nt][1] + bv.y);
        }
        const int m8 = m + 8;
        const int b8 = m8 >> 15, t8 = (m8 >> 6) & 511, n8 = m8 & 63;
        __half* dst8 = outp + ((size_t)((b8 * NHc + n8) * Tt + t8)) * 512;
#pragma unroll
        for (int nt = 0; nt < 4; nt++) {
            const int c = n0 + nfrag + nt * 8 + kq * 2;
            float2 bv = *(const float2*)(bias + c);
            *(__half2*)(dst8 + c) =
                __floats2half2_rn(acc[mt][nt][2] + bv.x, acc[mt][nt][3] + bv.y);
        }
    }
}

// ---------------- Fused attention (R9 configuration — measured best) ----------------
__global__ __launch_bounds__(512, 1)
void attn_fused(float* __restrict__ Outg,
                const float* __restrict__ lg, const float* __restrict__ lt)
{
    extern __shared__ __half sm[];
    float* rsum = (float*)(sm + 114688);  // after P(128KB)+stages(96KB)
    float* invl = rsum + 512;
    const uint32_t smbase  = smem_u32(sm);
    const uint32_t pbase   = smbase;           // P: [0, 131072)
    const uint32_t stgbase = smbase + 131072;  // 96KB stage region

    const int tid = threadIdx.x;
    const int wid = tid >> 5, lane = tid & 31;
    const int wm = wid >> 2, wn = wid & 3;
    const int mfrag = wm * 32;
    const int nfrag = wn * 32;      // phase-1 n base (32-wide)
    const int nfrag2 = wn * 64;     // phase-2 d base (64-wide)
    const int rq = lane >> 2, kq = lane & 3;
    const int m0 = blockIdx.x * 128;
    const int h  = blockIdx.y;
    const int b  = h >> 6, n = h & 63;

    const __half* Qh = g_Q + (size_t)h * (Tt * Dd) + (size_t)m0 * 512;
    const __half* Kh = g_K + (size_t)h * (Tt * Dd);
    const __half* Vh = g_V + (size_t)h * (Tt * Dd);

    const float gamma = fmaxf(__expf(*lg), 0.01f);
    const float tau   = fmaxf(__expf(*lt), 0.01f);
    const float scale = 1.0f / (22.62741699796952f * tau);

    // Phase-1 staging (128B rows): thread -> row tid>>2, chunks (tid&3)*2, +1
    const int srow = tid >> 2;
    const int ch0  = (tid & 3) * 2;
    uint32_t sw[2];
#pragma unroll
    for (int i = 0; i < 2; i++)
        sw[i] = (uint32_t)srow * 128 + (uint32_t)(((ch0 + i) ^ (srow & 7)) << 4);

    // Phase-2 V staging (512B rows, 32 rows/stage): row tid>>4, chunks tid&15, +16
    const int vrow = tid >> 4;
    const int vc0  = tid & 15;
    const uint32_t vswA = (uint32_t)vrow * 512 + (uint32_t)((vc0 ^ (vrow & 7)) << 4);
    const uint32_t vswB = vswA + 256;   // chunk+16: bit4 untouched by ^(row&7)

    const int aChunkLo = lane >> 4;
    const int bChunkLo = (lane >> 3) & 1;
    uint32_t aRowOff[2]; int aSw[2];
#pragma unroll
    for (int mt = 0; mt < 2; mt++) {
        int row = mfrag + mt * 16 + (lane & 15);
        aRowOff[mt] = (uint32_t)row * 128; aSw[mt] = row & 7;
    }
    uint32_t bRowOff[2]; int bSw[2];
#pragma unroll
    for (int ntp = 0; ntp < 2; ntp++) {
        int row = nfrag + ntp * 16 + (lane & 7) + ((lane >> 4) << 3);
        bRowOff[ntp] = (uint32_t)row * 128; bSw[ntp] = row & 7;
    }
    uint32_t pRowOff[2]; int pSw[2];
#pragma unroll
    for (int mt = 0; mt < 2; mt++) {
        int row = mfrag + mt * 16 + (lane & 15);
        pRowOff[mt] = (uint32_t)row * 1024; pSw[mt] = row & 7;
    }

    float rs[4] = {0.f, 0.f, 0.f, 0.f};
    const __half* Arow = Qh + (size_t)srow * 512 + ch0 * 8;

    // =============== Phase 1: flat 32 stages (4 jt x 8 k-stages) ===============
    auto issue1 = [&](int s) {
        const int jt = s >> 3, sk = s & 7;
        uint32_t ab = stgbase + (uint32_t)(s % 3) * 32768;
        uint32_t bb = ab + 16384;
        const __half* ag = Arow + sk * 64;
        const __half* bg = Kh + (size_t)(jt * 128 + srow) * 512 + ch0 * 8 + sk * 64;
#pragma unroll
        for (int i = 0; i < 2; i++) {
            cp_async16(ab + sw[i], ag + i * 8);
            cp_async16(bb + sw[i], bg + i * 8);
        }
        cp_commit();
    };

    {
        float acc[2][4][4];
#pragma unroll
        for (int mt = 0; mt < 2; mt++)
#pragma unroll
            for (int nt = 0; nt < 4; nt++)
#pragma unroll
                for (int e = 0; e < 4; e++) acc[mt][nt][e] = 0.f;

        issue1(0); issue1(1);
#pragma unroll 1
        for (int s = 0; s < 32; s++) {
            if (s < 31) cp_wait<1>(); else cp_wait<0>();
            __syncthreads();
            uint32_t ab = stgbase + (uint32_t)(s % 3) * 32768;
            uint32_t bb = ab + 16384;
#pragma unroll
            for (int ks = 0; ks < 4; ks++) {
                uint32_t afr[2][4], bfr[4][2];
#pragma unroll
                for (int mt = 0; mt < 2; mt++)
                    ldsm_x4(afr[mt][0], afr[mt][1], afr[mt][2], afr[mt][3],
                            ab + aRowOff[mt] + (uint32_t)(((ks * 2 + aChunkLo) ^ aSw[mt]) << 4));
#pragma unroll
                for (int ntp = 0; ntp < 2; ntp++) {
                    uint32_t r0, r1, r2, r3;
                    ldsm_x4(r0, r1, r2, r3,
                            bb + bRowOff[ntp] + (uint32_t)(((ks * 2 + bChunkLo) ^ bSw[ntp]) << 4));
                    bfr[2 * ntp][0] = r0; bfr[2 * ntp][1] = r1;
                    bfr[2 * ntp + 1][0] = r2; bfr[2 * ntp + 1][1] = r3;
                }
#pragma unroll
                for (int mt = 0; mt < 2; mt++)
#pragma unroll
                    for (int nt = 0; nt < 4; nt++)
                        mma_f16(acc[mt][nt][0], acc[mt][nt][1], acc[mt][nt][2], acc[mt][nt][3],
                                afr[mt][0], afr[mt][1], afr[mt][2], afr[mt][3],
                                bfr[nt][0], bfr[nt][1]);
            }
            if (s + 2 < 32) issue1(s + 2);

            if ((s & 7) == 7) {
                const int jt = s >> 3;
#pragma unroll
                for (int mt = 0; mt < 2; mt++) {
                    const int r  = mfrag + mt * 16 + rq;
                    const int t0 = m0 + r, t1 = t0 + 8;
#pragma unroll
                    for (int nt = 0; nt < 4; nt++) {
                        const int c  = nfrag + nt * 8 + kq * 2;
                        const int sg = jt * 128 + c;
                        float e00 = __expf(fmaf(acc[mt][nt][0], scale, decay_log(gamma, t0 - sg)));
                        float e01 = __expf(fmaf(acc[mt][nt][1], scale, decay_log(gamma, t0 - sg - 1)));
                        float e10 = __expf(fmaf(acc[mt][nt][2], scale, decay_log(gamma, t1 - sg)));
                        float e11 = __expf(fmaf(acc[mt][nt][3], scale, decay_log(gamma, t1 - sg - 1)));
                        uint32_t hoff0 = (uint32_t)r * 512 + (uint32_t)((((sg >> 3) ^ (r & 7)) << 3) + (sg & 7));
                        uint32_t hoff1 = (uint32_t)(r + 8) * 512 + (uint32_t)((((sg >> 3) ^ ((r + 8) & 7)) << 3) + (sg & 7));
                        *(__half2*)(sm + hoff0) = __floats2half2_rn(e00, e01);
                        *(__half2*)(sm + hoff1) = __floats2half2_rn(e10, e11);
                        rs[mt * 2 + 0] += e00 + e01;
                        rs[mt * 2 + 1] += e10 + e11;
                        acc[mt][nt][0] = 0.f; acc[mt][nt][1] = 0.f;
                        acc[mt][nt][2] = 0.f; acc[mt][nt][3] = 0.f;
                    }
                }
            }
        }
    }

    // rowsum reduce
#pragma unroll
    for (int i = 0; i < 4; i++) {
        rs[i] += __shfl_xor_sync(0xffffffffu, rs[i], 1);
        rs[i] += __shfl_xor_sync(0xffffffffu, rs[i], 2);
    }
    if (kq == 0) {
#pragma unroll
        for (int mt = 0; mt < 2; mt++) {
            const int r = mfrag + mt * 16 + rq;
            rsum[wn * 128 + r]     = rs[mt * 2 + 0];
            rsum[wn * 128 + r + 8] = rs[mt * 2 + 1];
        }
    }
    __syncthreads();
    if (tid < 128)
        invl[tid] = 1.0f / (rsum[tid] + rsum[128 + tid] + rsum[256 + tid] + rsum[384 + tid]);
    __syncthreads();

    // =============== Phase 2: 2 dc passes x 16 s-stages, 6-slot ring ===============
    auto issue2 = [&](int s) {
        const int dc = s >> 4, sk = s & 15;
        uint32_t bb = stgbase + (uint32_t)(s % 6) * 16384;
        const __half* bg = Vh + (size_t)(sk * 32 + vrow) * 512 + dc * 256;
        cp_async16(bb + vswA, bg + vc0 * 8);
        cp_async16(bb + vswB, bg + (vc0 + 16) * 8);
        cp_commit();
    };

    {
        float acc[2][8][4];
#pragma unroll
        for (int mt = 0; mt < 2; mt++)
#pragma unroll
            for (int nt = 0; nt < 8; nt++)
#pragma unroll
                for (int e = 0; e < 4; e++) acc[mt][nt][e] = 0.f;

        issue2(0); issue2(1); issue2(2); issue2(3); issue2(4);
#pragma unroll 1
        for (int s = 0; s < 32; s++) {
            if (s <= 27)      cp_wait<4>();
            else if (s == 28) cp_wait<3>();
            else if (s == 29) cp_wait<2>();
            else if (s == 30) cp_wait<1>();
            else              cp_wait<0>();
            __syncthreads();
            const int sk = s & 15;
            uint32_t bb = stgbase + (uint32_t)(s % 6) * 16384;
#pragma unroll
            for (int ks = 0; ks < 2; ks++) {
                uint32_t afr[2][4], bfr[8][2];
                const uint32_t achunk = (uint32_t)((sk * 2 + ks) * 2 + aChunkLo);
#pragma unroll
                for (int mt = 0; mt < 2; mt++)
                    ldsm_x4(afr[mt][0], afr[mt][1], afr[mt][2], afr[mt][3],
                            pbase + pRowOff[mt] + ((achunk ^ (uint32_t)pSw[mt]) << 4));
                const int rowk = ks * 16 + (lane & 15);
#pragma unroll
                for (int ntp = 0; ntp < 4; ntp++) {
                    uint32_t chunk = (uint32_t)((nfrag2 >> 3) + ntp * 2 + (lane >> 4));
                    uint32_t addr = bb + (uint32_t)rowk * 512
                                  + ((chunk ^ (uint32_t)(rowk & 7)) << 4);
                    uint32_t r0, r1, r2, r3;
                    ldsm_x4_t(r0, r1, r2, r3, addr);
                    bfr[2 * ntp][0] = r0; bfr[2 * ntp][1] = r1;
                    bfr[2 * ntp + 1][0] = r2; bfr[2 * ntp + 1][1] = r3;
                }
#pragma unroll
                for (int mt = 0; mt < 2; mt++)
#pragma unroll
                    for (int nt = 0; nt < 8; nt++)
                        mma_f16(acc[mt][nt][0], acc[mt][nt][1], acc[mt][nt][2], acc[mt][nt][3],
                                afr[mt][0], afr[mt][1], afr[mt][2], afr[mt][3],
                                bfr[nt][0], bfr[nt][1]);
            }
            if (s + 5 < 32) issue2(s + 5);

            if ((s & 15) == 15) {
                const int dc = s >> 4;
#pragma unroll
                for (int mt = 0; mt < 2; mt++) {
                    const int r = mfrag + mt * 16 + rq;
                    const float il0 = invl[r], il1 = invl[r + 8];
                    const int t0 = m0 + r;
                    float* dst0 = Outg + (((size_t)(b * Tt + t0) * NHc + n) << 9);
                    float* dst1 = Outg + (((size_t)(b * Tt + t0 + 8) * NHc + n) << 9);
#pragma unroll
                    for (int nt = 0; nt < 8; nt++) {
                        const int c = dc * 256 + nfrag2 + nt * 8 + kq * 2;
                        float2 v0 = { acc[mt][nt][0] * il0, acc[mt][nt][1] * il0 };
                        float2 v1 = { acc[mt][nt][2] * il1, acc[mt][nt][3] * il1 };
                        *(float2*)(dst0 + c) = v0;
                        *(float2*)(dst1 + c) = v1;
                        acc[mt][nt][0] = 0.f; acc[mt][nt][1] = 0.f;
                        acc[mt][nt][2] = 0.f; acc[mt][nt][3] = 0.f;
                    }
                }
            }
        }
    }
}

extern "C" void kernel_launch(void* const* d_in, const int* in_sizes, int n_in,
                              void* d_out, int out_size)
{
    const float* H_i = (const float*)d_in[0];
    const float* H_j = (const float*)d_in[1];
    const float* Wq  = (const float*)d_in[2];
    const float* bq  = (const float*)d_in[3];
    const float* Wk  = (const float*)d_in[4];
    const float* bk  = (const float*)d_in[5];
    const float* Wv  = (const float*)d_in[6];
    const float* bv  = (const float*)d_in[7];
    const float* lg  = (const float*)d_in[8];
    const float* lt  = (const float*)d_in[9];
    float* out = (float*)d_out;

    // Convert only W to f16 (one launch); H is consumed as f32 by proj_gemm.
    w_to_half<<<dim3(256, 3), 256>>>(Wq, Wk, Wv);

    const int proj_shmem = 3 * 32768;  // 96KB
    cudaFuncSetAttribute(proj_gemm, cudaFuncAttributeMaxDynamicSharedMemorySize, proj_shmem);

    dim3 gproj(4, MPROJ / 128, 3);     // x = n-tile (L2-shared A), y = m-tile, z = Q/K/V
    proj_gemm<<<gproj, 256, proj_shmem>>>(H_i, H_j, bq, bk, bv);

    // P 128KB + 96KB stage region + rsum(2KB) + invl(512B) = 231936 B
    const int attn_shmem = 131072 + 98304 + 2048 + 512;
    cudaFuncSetAttribute(attn_fused, cudaFuncAttributeMaxDynamicSharedMemorySize, attn_shmem);
    attn_fused<<<dim3(4, NHEADS), 512, attn_shmem>>>(out, lg, lt);
}

// round 14
// speedup vs baseline: 1.3749x; 1.3749x over previous
#include <cuda_runtime.h>
#include <cuda_fp16.h>
#include <cstdint>
#include <math.h>

constexpr int Tt = 512, NHc = 64, Dd = 512, Bb = 4;
constexpr int NHEADS = Bb * NHc;        // 256
constexpr int MPROJ  = Bb * Tt * NHc;   // 131072

// Scratch (device globals; no cudaMalloc allowed)
__device__ __half g_Hi[(size_t)MPROJ * Dd];
__device__ __half g_Hj[(size_t)MPROJ * Dd];
__device__ __half g_Wq[(size_t)Dd * Dd];
__device__ __half g_Wk[(size_t)Dd * Dd];
__device__ __half g_Wv[(size_t)Dd * Dd];
__device__ __half g_Q [(size_t)MPROJ * Dd];        // [B,N,T,D] head-major
__device__ __half g_K [(size_t)MPROJ * Dd];        // [B,N,S,D] head-major
__device__ __half g_V [(size_t)MPROJ * Dd];        // [B,N,S,D] head-major

__device__ __forceinline__ uint32_t smem_u32(const void* p) {
    uint32_t a;
    asm("{ .reg .u64 t; cvta.to.shared.u64 t, %1; cvt.u32.u64 %0, t; }" : "=r"(a) : "l"(p));
    return a;
}
__device__ __forceinline__ void cp_async16(uint32_t saddr, const void* gptr) {
    asm volatile("cp.async.cg.shared.global [%0], [%1], 16;" :: "r"(saddr), "l"(gptr));
}
__device__ __forceinline__ void cp_commit() {
    asm volatile("cp.async.commit_group;" ::: "memory");
}
template<int N> __device__ __forceinline__ void cp_wait() {
    asm volatile("cp.async.wait_group %0;" :: "n"(N) : "memory");
}
__device__ __forceinline__ void ldsm_x4(uint32_t& r0, uint32_t& r1, uint32_t& r2, uint32_t& r3,
                                        uint32_t a) {
    asm volatile("ldmatrix.sync.aligned.m8n8.x4.shared.b16 {%0,%1,%2,%3}, [%4];"
                 : "=r"(r0), "=r"(r1), "=r"(r2), "=r"(r3) : "r"(a));
}
__device__ __forceinline__ void ldsm_x4_t(uint32_t& r0, uint32_t& r1, uint32_t& r2, uint32_t& r3,
                                          uint32_t a) {
    asm volatile("ldmatrix.sync.aligned.m8n8.x4.trans.shared.b16 {%0,%1,%2,%3}, [%4];"
                 : "=r"(r0), "=r"(r1), "=r"(r2), "=r"(r3) : "r"(a));
}
__device__ __forceinline__ void mma_f16(float& d0, float& d1, float& d2, float& d3,
                                        uint32_t a0, uint32_t a1, uint32_t a2, uint32_t a3,
                                        uint32_t b0, uint32_t b1) {
    asm volatile(
        "mma.sync.aligned.m16n8k16.row.col.f32.f16.f16.f32 "
        "{%0,%1,%2,%3}, {%4,%5,%6,%7}, {%8,%9}, {%0,%1,%2,%3};"
        : "+f"(d0), "+f"(d1), "+f"(d2), "+f"(d3)
        : "r"(a0), "r"(a1), "r"(a2), "r"(a3), "r"(b0), "r"(b1));
}
__device__ __forceinline__ float decay_log(float gamma, int dt) {
    float gd = gamma * fabsf((float)dt) * (1.0f / 511.0f);
    return (gd < 11.0f) ? -gd : logf(expf(-gd) + 1e-8f);
}

// ---------------- f32 -> f16 pre-pass: ONE launch for all 5 tensors ----------------
// grid (4096, 5): z=0 -> H_i, z=1 -> H_j, z=2..4 -> Wq/Wk/Wv.
__global__ __launch_bounds__(256)
void to_half_all(const float* __restrict__ Hi, const float* __restrict__ Hj,
                 const float* __restrict__ Wq, const float* __restrict__ Wk,
                 const float* __restrict__ Wv)
{
    const int which = blockIdx.y;
    const float* src;
    __half* dst;
    size_t n4;
    if (which == 0)      { src = Hi; dst = g_Hi; n4 = (size_t)MPROJ * Dd / 4; }
    else if (which == 1) { src = Hj; dst = g_Hj; n4 = (size_t)MPROJ * Dd / 4; }
    else if (which == 2) { src = Wq; dst = g_Wq; n4 = (size_t)Dd * Dd / 4; }
    else if (which == 3) { src = Wk; dst = g_Wk; n4 = (size_t)Dd * Dd / 4; }
    else                 { src = Wv; dst = g_Wv; n4 = (size_t)Dd * Dd / 4; }

    size_t i = (size_t)blockIdx.x * blockDim.x + threadIdx.x;
    size_t stride = (size_t)gridDim.x * blockDim.x;
    for (; i < n4; i += stride) {
        float4 v = ((const float4*)src)[i];
        __half2 h0 = __floats2half2_rn(v.x, v.y);
        __half2 h1 = __floats2half2_rn(v.z, v.w);
        uint2 u = { *(uint32_t*)&h0, *(uint32_t*)&h1 };
        ((uint2*)dst)[i] = u;
    }
}

// ---------------- Projection GEMM (fp16 mma, head-major store) ----------------
// ONE launch covers Q/K/V via blockIdx.z; grid (4 n-tiles, 1024 m-tiles, 3).
__global__ __launch_bounds__(256, 2)
void proj_gemm(const __half* __restrict__ Hi, const __half* __restrict__ Hj,
               const __half* __restrict__ Wq, const __half* __restrict__ Wk,
               const __half* __restrict__ Wv,
               const float* __restrict__ bq, const float* __restrict__ bk,
               const float* __restrict__ bv)
{
    extern __shared__ __half sm[];   // 3 bufs x (A 16KB | B 16KB) = 96KB
    const uint32_t smbase = smem_u32(sm);

    const int tid = threadIdx.x;
    const int wid = tid >> 5, lane = tid & 31;
    const int wm = wid >> 2, wn = wid & 3;
    const int m0 = blockIdx.y * 128;
    const int n0 = blockIdx.x * 128;
    const int which = blockIdx.z;

    const __half* Ag = (which == 0) ? Hi : Hj;
    const __half* Bg = (which == 0) ? Wq : (which == 1) ? Wk : Wv;
    const float* bias = (which == 0) ? bq : (which == 1) ? bk : bv;

    const __half* A = Ag + (size_t)m0 * 512;
    const __half* B = Bg + (size_t)n0 * 512;

    const int srow = tid >> 1;
    const int cb0  = (tid & 1) * 4;
    const __half* agp = A + (size_t)srow * 512 + cb0 * 8;
    const __half* bgp = B + (size_t)srow * 512 + cb0 * 8;
    uint32_t swoff[4];
#pragma unroll
    for (int i = 0; i < 4; i++)
        swoff[i] = (uint32_t)srow * 128 + (uint32_t)(((cb0 + i) ^ (srow & 7)) << 4);

    auto issue = [&](int s) {
        uint32_t ab = smbase + (uint32_t)(s % 3) * 32768;
        uint32_t bb = ab + 16384;
        const __half* ag = agp + s * 64;
        const __half* bg = bgp + s * 64;
#pragma unroll
        for (int i = 0; i < 4; i++) {
            cp_async16(ab + swoff[i], ag + i * 8);
            cp_async16(bb + swoff[i], bg + i * 8);
        }
        cp_commit();
    };

    const int mfrag = wm * 64, nfrag = wn * 32;
    const int aChunkLo = lane >> 4;
    const int bChunkLo = (lane >> 3) & 1;
    uint32_t aRowOff[4]; int aSw[4];
#pragma unroll
    for (int mt = 0; mt < 4; mt++) {
        int row = mfrag + mt * 16 + (lane & 15);
        aRowOff[mt] = (uint32_t)row * 128; aSw[mt] = row & 7;
    }
    uint32_t bRowOff[2]; int bSw[2];
#pragma unroll
    for (int ntp = 0; ntp < 2; ntp++) {
        int row = nfrag + ntp * 16 + (lane & 7) + ((lane >> 4) << 3);
        bRowOff[ntp] = (uint32_t)row * 128; bSw[ntp] = row & 7;
    }

    float acc[4][4][4];
#pragma unroll
    for (int mt = 0; mt < 4; mt++)
#pragma unroll
        for (int nt = 0; nt < 4; nt++)
#pragma unroll
            for (int e = 0; e < 4; e++) acc[mt][nt][e] = 0.f;

    issue(0); issue(1);
#pragma unroll 1
    for (int s = 0; s < 8; s++) {
        if (s < 7) cp_wait<1>(); else cp_wait<0>();
        __syncthreads();
        uint32_t ab = smbase + (uint32_t)(s % 3) * 32768;
        uint32_t bb = ab + 16384;
#pragma unroll
        for (int ks = 0; ks < 4; ks++) {
            uint32_t afr[4][4], bfr[4][2];
#pragma unroll
            for (int mt = 0; mt < 4; mt++)
                ldsm_x4(afr[mt][0], afr[mt][1], afr[mt][2], afr[mt][3],
                        ab + aRowOff[mt] + (uint32_t)(((ks * 2 + aChunkLo) ^ aSw[mt]) << 4));
#pragma unroll
            for (int ntp = 0; ntp < 2; ntp++) {
                uint32_t r0, r1, r2, r3;
                ldsm_x4(r0, r1, r2, r3,
                        bb + bRowOff[ntp] + (uint32_t)(((ks * 2 + bChunkLo) ^ bSw[ntp]) << 4));
                bfr[2 * ntp][0] = r0; bfr[2 * ntp][1] = r1;
                bfr[2 * ntp + 1][0] = r2; bfr[2 * ntp + 1][1] = r3;
            }
#pragma unroll
            for (int mt = 0; mt < 4; mt++)
#pragma unroll
                for (int nt = 0; nt < 4; nt++)
                    mma_f16(acc[mt][nt][0], acc[mt][nt][1], acc[mt][nt][2], acc[mt][nt][3],
                            afr[mt][0], afr[mt][1], afr[mt][2], afr[mt][3],
                            bfr[nt][0], bfr[nt][1]);
        }
        if (s + 2 < 8) issue(s + 2);
    }

    const int rq = lane >> 2, kq = lane & 3;
    __half* outp = (which == 0) ? g_Q : (which == 1) ? g_K : g_V;
#pragma unroll
    for (int mt = 0; mt < 4; mt++) {
        const int m = m0 + mfrag + mt * 16 + rq;
        const int b = m >> 15, t = (m >> 6) & 511, n = m & 63;
        __half* dst0 = outp + ((size_t)((b * NHc + n) * Tt + t)) * 512;
#pragma unroll
        for (int nt = 0; nt < 4; nt++) {
            const int c = n0 + nfrag + nt * 8 + kq * 2;
            float2 bv = *(const float2*)(bias + c);
            *(__half2*)(dst0 + c) =
                __floats2half2_rn(acc[mt][nt][0] + bv.x, acc[mt][nt][1] + bv.y);
        }
        const int m8 = m + 8;
        const int b8 = m8 >> 15, t8 = (m8 >> 6) & 511, n8 = m8 & 63;
        __half* dst8 = outp + ((size_t)((b8 * NHc + n8) * Tt + t8)) * 512;
#pragma unroll
        for (int nt = 0; nt < 4; nt++) {
            const int c = n0 + nfrag + nt * 8 + kq * 2;
            float2 bv = *(const float2*)(bias + c);
            *(__half2*)(dst8 + c) =
                __floats2half2_rn(acc[mt][nt][2] + bv.x, acc[mt][nt][3] + bv.y);
        }
    }
}

// ---------------- Fused attention (R9/R12 configuration — measured best) ----------------
__global__ __launch_bounds__(512, 1)
void attn_fused(float* __restrict__ Outg,
                const float* __restrict__ lg, const float* __restrict__ lt)
{
    extern __shared__ __half sm[];
    float* rsum = (float*)(sm + 114688);  // after P(128KB)+stages(96KB)
    float* invl = rsum + 512;
    const uint32_t smbase  = smem_u32(sm);
    const uint32_t pbase   = smbase;           // P: [0, 131072)
    const uint32_t stgbase = smbase + 131072;  // 96KB stage region

    const int tid = threadIdx.x;
    const int wid = tid >> 5, lane = tid & 31;
    const int wm = wid >> 2, wn = wid & 3;
    const int mfrag = wm * 32;
    const int nfrag = wn * 32;      // phase-1 n base (32-wide)
    const int nfrag2 = wn * 64;     // phase-2 d base (64-wide)
    const int rq = lane >> 2, kq = lane & 3;
    const int m0 = blockIdx.x * 128;
    const int h  = blockIdx.y;
    const int b  = h >> 6, n = h & 63;

    const __half* Qh = g_Q + (size_t)h * (Tt * Dd) + (size_t)m0 * 512;
    const __half* Kh = g_K + (size_t)h * (Tt * Dd);
    const __half* Vh = g_V + (size_t)h * (Tt * Dd);

    const float gamma = fmaxf(__expf(*lg), 0.01f);
    const float tau   = fmaxf(__expf(*lt), 0.01f);
    const float scale = 1.0f / (22.62741699796952f * tau);

    // Phase-1 staging (128B rows): thread -> row tid>>2, chunks (tid&3)*2, +1
    const int srow = tid >> 2;
    const int ch0  = (tid & 3) * 2;
    uint32_t sw[2];
#pragma unroll
    for (int i = 0; i < 2; i++)
        sw[i] = (uint32_t)srow * 128 + (uint32_t)(((ch0 + i) ^ (srow & 7)) << 4);

    // Phase-2 V staging (512B rows, 32 rows/stage): row tid>>4, chunks tid&15, +16
    const int vrow = tid >> 4;
    const int vc0  = tid & 15;
    const uint32_t vswA = (uint32_t)vrow * 512 + (uint32_t)((vc0 ^ (vrow & 7)) << 4);
    const uint32_t vswB = vswA + 256;   // chunk+16: bit4 untouched by ^(row&7)

    const int aChunkLo = lane >> 4;
    const int bChunkLo = (lane >> 3) & 1;
    uint32_t aRowOff[2]; int aSw[2];
#pragma unroll
    for (int mt = 0; mt < 2; mt++) {
        int row = mfrag + mt * 16 + (lane & 15);
        aRowOff[mt] = (uint32_t)row * 128; aSw[mt] = row & 7;
    }
    uint32_t bRowOff[2]; int bSw[2];
#pragma unroll
    for (int ntp = 0; ntp < 2; ntp++) {
        int row = nfrag + ntp * 16 + (lane & 7) + ((lane >> 4) << 3);
        bRowOff[ntp] = (uint32_t)row * 128; bSw[ntp] = row & 7;
    }
    uint32_t pRowOff[2]; int pSw[2];
#pragma unroll
    for (int mt = 0; mt < 2; mt++) {
        int row = mfrag + mt * 16 + (lane & 15);
        pRowOff[mt] = (uint32_t)row * 1024; pSw[mt] = row & 7;
    }

    float rs[4] = {0.f, 0.f, 0.f, 0.f};
    const __half* Arow = Qh + (size_t)srow * 512 + ch0 * 8;

    // =============== Phase 1: flat 32 stages (4 jt x 8 k-stages) ===============
    auto issue1 = [&](int s) {
        const int jt = s >> 3, sk = s & 7;
        uint32_t ab = stgbase + (uint32_t)(s % 3) * 32768;
        uint32_t bb = ab + 16384;
        const __half* ag = Arow + sk * 64;
        const __half* bg = Kh + (size_t)(jt * 128 + srow) * 512 + ch0 * 8 + sk * 64;
#pragma unroll
        for (int i = 0; i < 2; i++) {
            cp_async16(ab + sw[i], ag + i * 8);
            cp_async16(bb + sw[i], bg + i * 8);
        }
        cp_commit();
    };

    {
        float acc[2][4][4];
#pragma unroll
        for (int mt = 0; mt < 2; mt++)
#pragma unroll
            for (int nt = 0; nt < 4; nt++)
#pragma unroll
                for (int e = 0; e < 4; e++) acc[mt][nt][e] = 0.f;

        issue1(0); issue1(1);
#pragma unroll 1
        for (int s = 0; s < 32; s++) {
            if (s < 31) cp_wait<1>(); else cp_wait<0>();
            __syncthreads();
            uint32_t ab = stgbase + (uint32_t)(s % 3) * 32768;
            uint32_t bb = ab + 16384;
#pragma unroll
            for (int ks = 0; ks < 4; ks++) {
                uint32_t afr[2][4], bfr[4][2];
#pragma unroll
                for (int mt = 0; mt < 2; mt++)
                    ldsm_x4(afr[mt][0], afr[mt][1], afr[mt][2], afr[mt][3],
                            ab + aRowOff[mt] + (uint32_t)(((ks * 2 + aChunkLo) ^ aSw[mt]) << 4));
#pragma unroll
                for (int ntp = 0; ntp < 2; ntp++) {
                    uint32_t r0, r1, r2, r3;
                    ldsm_x4(r0, r1, r2, r3,
                            bb + bRowOff[ntp] + (uint32_t)(((ks * 2 + bChunkLo) ^ bSw[ntp]) << 4));
                    bfr[2 * ntp][0] = r0; bfr[2 * ntp][1] = r1;
                    bfr[2 * ntp + 1][0] = r2; bfr[2 * ntp + 1][1] = r3;
                }
#pragma unroll
                for (int mt = 0; mt < 2; mt++)
#pragma unroll
                    for (int nt = 0; nt < 4; nt++)
                        mma_f16(acc[mt][nt][0], acc[mt][nt][1], acc[mt][nt][2], acc[mt][nt][3],
                                afr[mt][0], afr[mt][1], afr[mt][2], afr[mt][3],
                                bfr[nt][0], bfr[nt][1]);
            }
            if (s + 2 < 32) issue1(s + 2);

            if ((s & 7) == 7) {
                const int jt = s >> 3;
#pragma unroll
                for (int mt = 0; mt < 2; mt++) {
                    const int r  = mfrag + mt * 16 + rq;
                    const int t0 = m0 + r, t1 = t0 + 8;
#pragma unroll
                    for (int nt = 0; nt < 4; nt++) {
                        const int c  = nfrag + nt * 8 + kq * 2;
                        const int sg = jt * 128 + c;
                        float e00 = __expf(fmaf(acc[mt][nt][0], scale, decay_log(gamma, t0 - sg)));
                        float e01 = __expf(fmaf(acc[mt][nt][1], scale, decay_log(gamma, t0 - sg - 1)));
                        float e10 = __expf(fmaf(acc[mt][nt][2], scale, decay_log(gamma, t1 - sg)));
                        float e11 = __expf(fmaf(acc[mt][nt][3], scale, decay_log(gamma, t1 - sg - 1)));
                        uint32_t hoff0 = (uint32_t)r * 512 + (uint32_t)((((sg >> 3) ^ (r & 7)) << 3) + (sg & 7));
                        uint32_t hoff1 = (uint32_t)(r + 8) * 512 + (uint32_t)((((sg >> 3) ^ ((r + 8) & 7)) << 3) + (sg & 7));
                        *(__half2*)(sm + hoff0) = __floats2half2_rn(e00, e01);
                        *(__half2*)(sm + hoff1) = __floats2half2_rn(e10, e11);
                        rs[mt * 2 + 0] += e00 + e01;
                        rs[mt * 2 + 1] += e10 + e11;
                        acc[mt][nt][0] = 0.f; acc[mt][nt][1] = 0.f;
                        acc[mt][nt][2] = 0.f; acc[mt][nt][3] = 0.f;
                    }
                }
            }
        }
    }

    // rowsum reduce
#pragma unroll
    for (int i = 0; i < 4; i++) {
        rs[i] += __shfl_xor_sync(0xffffffffu, rs[i], 1);
        rs[i] += __shfl_xor_sync(0xffffffffu, rs[i], 2);
    }
    if (kq == 0) {
#pragma unroll
        for (int mt = 0; mt < 2; mt++) {
            const int r = mfrag + mt * 16 + rq;
            rsum[wn * 128 + r]     = rs[mt * 2 + 0];
            rsum[wn * 128 + r + 8] = rs[mt * 2 + 1];
        }
    }
    __syncthreads();
    if (tid < 128)
        invl[tid] = 1.0f / (rsum[tid] + rsum[128 + tid] + rsum[256 + tid] + rsum[384 + tid]);
    __syncthreads();

    // =============== Phase 2: 2 dc passes x 16 s-stages, 6-slot ring ===============
    auto issue2 = [&](int s) {
        const int dc = s >> 4, sk = s & 15;
        uint32_t bb = stgbase + (uint32_t)(s % 6) * 16384;
        const __half* bg = Vh + (size_t)(sk * 32 + vrow) * 512 + dc * 256;
        cp_async16(bb + vswA, bg + vc0 * 8);
        cp_async16(bb + vswB, bg + (vc0 + 16) * 8);
        cp_commit();
    };

    {
        float acc[2][8][4];
#pragma unroll
        for (int mt = 0; mt < 2; mt++)
#pragma unroll
            for (int nt = 0; nt < 8; nt++)
#pragma unroll
                for (int e = 0; e < 4; e++) acc[mt][nt][e] = 0.f;

        issue2(0); issue2(1); issue2(2); issue2(3); issue2(4);
#pragma unroll 1
        for (int s = 0; s < 32; s++) {
            if (s <= 27)      cp_wait<4>();
            else if (s == 28) cp_wait<3>();
            else if (s == 29) cp_wait<2>();
            else if (s == 30) cp_wait<1>();
            else              cp_wait<0>();
            __syncthreads();
            const int sk = s & 15;
            uint32_t bb = stgbase + (uint32_t)(s % 6) * 16384;
#pragma unroll
            for (int ks = 0; ks < 2; ks++) {
                uint32_t afr[2][4], bfr[8][2];
                const uint32_t achunk = (uint32_t)((sk * 2 + ks) * 2 + aChunkLo);
#pragma unroll
                for (int mt = 0; mt < 2; mt++)
                    ldsm_x4(afr[mt][0], afr[mt][1], afr[mt][2], afr[mt][3],
                            pbase + pRowOff[mt] + ((achunk ^ (uint32_t)pSw[mt]) << 4));
                const int rowk = ks * 16 + (lane & 15);
#pragma unroll
                for (int ntp = 0; ntp < 4; ntp++) {
                    uint32_t chunk = (uint32_t)((nfrag2 >> 3) + ntp * 2 + (lane >> 4));
                    uint32_t addr = bb + (uint32_t)rowk * 512
                                  + ((chunk ^ (uint32_t)(rowk & 7)) << 4);
                    uint32_t r0, r1, r2, r3;
                    ldsm_x4_t(r0, r1, r2, r3, addr);
                    bfr[2 * ntp][0] = r0; bfr[2 * ntp][1] = r1;
                    bfr[2 * ntp + 1][0] = r2; bfr[2 * ntp + 1][1] = r3;
                }
#pragma unroll
                for (int mt = 0; mt < 2; mt++)
#pragma unroll
                    for (int nt = 0; nt < 8; nt++)
                        mma_f16(acc[mt][nt][0], acc[mt][nt][1], acc[mt][nt][2], acc[mt][nt][3],
                                afr[mt][0], afr[mt][1], afr[mt][2], afr[mt][3],
                                bfr[nt][0], bfr[nt][1]);
            }
            if (s + 5 < 32) issue2(s + 5);

            if ((s & 15) == 15) {
                const int dc = s >> 4;
#pragma unroll
                for (int mt = 0; mt < 2; mt++) {
                    const int r = mfrag + mt * 16 + rq;
                    const float il0 = invl[r], il1 = invl[r + 8];
                    const int t0 = m0 + r;
                    float* dst0 = Outg + (((size_t)(b * Tt + t0) * NHc + n) << 9);
                    float* dst1 = Outg + (((size_t)(b * Tt + t0 + 8) * NHc + n) << 9);
#pragma unroll
                    for (int nt = 0; nt < 8; nt++) {
                        const int c = dc * 256 + nfrag2 + nt * 8 + kq * 2;
                        float2 v0 = { acc[mt][nt][0] * il0, acc[mt][nt][1] * il0 };
                        float2 v1 = { acc[mt][nt][2] * il1, acc[mt][nt][3] * il1 };
                        *(float2*)(dst0 + c) = v0;
                        *(float2*)(dst1 + c) = v1;
                        acc[mt][nt][0] = 0.f; acc[mt][nt][1] = 0.f;
                        acc[mt][nt][2] = 0.f; acc[mt][nt][3] = 0.f;
                    }
                }
            }
        }
    }
}

extern "C" void kernel_launch(void* const* d_in, const int* in_sizes, int n_in,
                              void* d_out, int out_size)
{
    const float* H_i = (const float*)d_in[0];
    const float* H_j = (const float*)d_in[1];
    const float* Wq  = (const float*)d_in[2];
    const float* bq  = (const float*)d_in[3];
    const float* Wk  = (const float*)d_in[4];
    const float* bk  = (const float*)d_in[5];
    const float* Wv  = (const float*)d_in[6];
    const float* bv  = (const float*)d_in[7];
    const float* lg  = (const float*)d_in[8];
    const float* lt  = (const float*)d_in[9];
    float* out = (float*)d_out;

    __half *p_Hi, *p_Hj, *p_Wq, *p_Wk, *p_Wv;
    cudaGetSymbolAddress((void**)&p_Hi, g_Hi);
    cudaGetSymbolAddress((void**)&p_Hj, g_Hj);
    cudaGetSymbolAddress((void**)&p_Wq, g_Wq);
    cudaGetSymbolAddress((void**)&p_Wk, g_Wk);
    cudaGetSymbolAddress((void**)&p_Wv, g_Wv);
    (void)p_Hi; (void)p_Hj; (void)p_Wq; (void)p_Wk; (void)p_Wv;

    // One conversion launch for H_i, H_j, Wq, Wk, Wv.
    to_half_all<<<dim3(4096, 5), 256>>>(H_i, H_j, Wq, Wk, Wv);

    const int proj_shmem = 3 * 32768;  // 96KB
    cudaFuncSetAttribute(proj_gemm, cudaFuncAttributeMaxDynamicSharedMemorySize, proj_shmem);

    dim3 gproj(4, MPROJ / 128, 3);     // x = n-tile (L2-shared A), y = m-tile, z = Q/K/V
    proj_gemm<<<gproj, 256, proj_shmem>>>(p_Hi, p_Hj, p_Wq, p_Wk, p_Wv, bq, bk, bv);

    // P 128KB + 96KB stage region + rsum(2KB) + invl(512B) = 231936 B
    const int attn_shmem = 131072 + 98304 + 2048 + 512;
    cudaFuncSetAttribute(attn_fused, cudaFuncAttributeMaxDynamicSharedMemorySize, attn_shmem);
    attn_fused<<<dim3(4, NHEADS), 512, attn_shmem>>>(out, lg, lt);
}